// round 12
// baseline (speedup 1.0000x reference)
#include <cuda_runtime.h>
#include <cuda_bf16.h>
#include <cstdint>
#include <cstddef>

#define T_STEPS 512
#define BATCH   64
#define DIMD    512
#define DIMH    512
#define N4H     2048   // 4 gates * H, packed as j' = hid*4 + gate
#define KDIM    512
#define HB      (DIMH * BATCH)      // 32768
#define MROWS   (T_STEPS * BATCH)   // 32768
#define KSPLIT  1536                // 3 * 512 (bf16x3 split segments)

// ---------------- device scratch (static) ----------------------------------------
__device__ float g_Xproj[(size_t)T_STEPS * BATCH * N4H];   // 256 MB [t*B+b][j']
__device__ unsigned g_hx[(size_t)T_STEPS * HB];            // 64 MB [t][b][hid] packed (hi|lo)
__device__ unsigned g_cx[HB];                              // final c packed [b][hid]
__device__ __nv_bfloat16 g_Ap[(size_t)MROWS * KSPLIT];     // 96 MB  A' = [hi | lo | hi]
__device__ __nv_bfloat16 g_Bp[(size_t)N4H * KSPLIT];       // 6 MB   B'[j'][k] = [hi | hi | lo]
__device__ __nv_bfloat16 g_Whh[(size_t)N4H * KDIM];        // 2 MB   Wh^T hi [j'][k]
__device__ __nv_bfloat16 g_Whl[(size_t)N4H * KDIM];        // 2 MB   Wh^T lo [j'][k]
__device__ unsigned long long g_flags[128];                // per-CTA monotone step flags

// ---------------- helpers ----------------------------------------------------------
static __device__ __forceinline__ float sigf(float x) {
    return __fdividef(1.0f, 1.0f + __expf(-x));
}
static __device__ __forceinline__ float tanh_(float x) {
    return 2.0f * sigf(2.0f * x) - 1.0f;
}
static __device__ __forceinline__ unsigned pack_hl(float v) {
    __nv_bfloat16 hb = __float2bfloat16(v);
    __nv_bfloat16 lb = __float2bfloat16(v - __bfloat162float(hb));
    return (unsigned)__bfloat16_as_ushort(hb) | ((unsigned)__bfloat16_as_ushort(lb) << 16);
}
static __device__ __forceinline__ float unpack_hl(unsigned u) {
    return __bfloat162float(__ushort_as_bfloat16((unsigned short)(u & 0xffffu)))
         + __bfloat162float(__ushort_as_bfloat16((unsigned short)(u >> 16)));
}
static __device__ __forceinline__ uint32_t smem_u32(const void* p) {
    uint32_t a;
    asm("{ .reg .u64 t; cvta.to.shared.u64 t, %1; cvt.u32.u64 %0, t; }" : "=r"(a) : "l"(p));
    return a;
}
static __device__ __forceinline__ void ldsm_x4(uint32_t* r, uint32_t addr) {
    asm volatile("ldmatrix.sync.aligned.m8n8.x4.shared.b16 {%0,%1,%2,%3}, [%4];"
                 : "=r"(r[0]), "=r"(r[1]), "=r"(r[2]), "=r"(r[3]) : "r"(addr));
}
static __device__ __forceinline__ void hmma16816(float* c, const uint32_t* a,
                                                 uint32_t b0, uint32_t b1) {
    asm volatile("mma.sync.aligned.m16n8k16.row.col.f32.bf16.bf16.f32 "
                 "{%0,%1,%2,%3}, {%4,%5,%6,%7}, {%8,%9}, {%0,%1,%2,%3};"
                 : "+f"(c[0]), "+f"(c[1]), "+f"(c[2]), "+f"(c[3])
                 : "r"(a[0]), "r"(a[1]), "r"(a[2]), "r"(a[3]), "r"(b0), "r"(b1));
}

// ---------------- pack kernels (bf16 hi/lo split) ---------------------------------
__global__ void pack_a(const float* __restrict__ X) {
    size_t idx = (size_t)blockIdx.x * blockDim.x + threadIdx.x;
    size_t stride = (size_t)gridDim.x * blockDim.x;
    for (size_t i = idx; i < (size_t)MROWS * KDIM; i += stride) {
        size_t m = i / KDIM, k = i % KDIM;
        float x = X[i];
        __nv_bfloat16 hi = __float2bfloat16(x);
        __nv_bfloat16 lo = __float2bfloat16(x - __bfloat162float(hi));
        __nv_bfloat16* row = g_Ap + m * KSPLIT;
        row[k] = hi; row[512 + k] = lo; row[1024 + k] = hi;
    }
}
__global__ void pack_b(const float* __restrict__ Wf, const float* __restrict__ Wi,
                       const float* __restrict__ Wg, const float* __restrict__ Wo) {
    size_t idx = (size_t)blockIdx.x * blockDim.x + threadIdx.x;
    size_t stride = (size_t)gridDim.x * blockDim.x;
    for (size_t i = idx; i < (size_t)N4H * KDIM; i += stride) {
        size_t j = i / KDIM, k = i % KDIM;
        int g = (int)(j & 3), c = (int)(j >> 2);
        const float* W = (g == 0) ? Wf : (g == 1) ? Wi : (g == 2) ? Wg : Wo;
        float w = W[k * DIMH + c];
        __nv_bfloat16 hi = __float2bfloat16(w);
        __nv_bfloat16 lo = __float2bfloat16(w - __bfloat162float(hi));
        __nv_bfloat16* row = g_Bp + j * KSPLIT;
        row[k] = hi; row[512 + k] = hi; row[1024 + k] = lo;
        float wh = W[(size_t)(DIMD + k) * DIMH + c];
        __nv_bfloat16 hh = __float2bfloat16(wh);
        __nv_bfloat16 hl = __float2bfloat16(wh - __bfloat162float(hh));
        g_Whh[j * KDIM + k] = hh;
        g_Whl[j * KDIM + k] = hl;
    }
}

// ---------------- kernel: xproj GEMM via mma.sync (bf16x3, fp32 accum) ------------
#define XBM 128
#define XBN 128
#define XBK 32
#define XROWS 40

__global__ __launch_bounds__(256) void xproj_mma(
        const float* __restrict__ bf, const float* __restrict__ bi,
        const float* __restrict__ bg, const float* __restrict__ bo) {
    __shared__ __nv_bfloat16 As[2][XBM * XROWS];
    __shared__ __nv_bfloat16 Bs[2][XBN * XROWS];
    __shared__ float bsm[XBN];

    const int tid  = threadIdx.x;
    const int lane = tid & 31;
    const int wid  = tid >> 5;
    const int wm   = wid & 1;
    const int wn   = wid >> 1;
    const int m0   = blockIdx.y * XBM;
    const int n0   = blockIdx.x * XBN;

    if (tid < XBN) {
        int j = n0 + tid, g = j & 3, c = j >> 2;
        bsm[tid] = (g == 0 ? bf : g == 1 ? bi : g == 2 ? bg : bo)[c];
    }

    float acc[4][4][4];
#pragma unroll
    for (int a = 0; a < 4; ++a)
#pragma unroll
        for (int b = 0; b < 4; ++b)
#pragma unroll
            for (int q = 0; q < 4; ++q) acc[a][b][q] = 0.0f;

    const int lrow = tid >> 1;
    const int lofs = (tid & 1) * 16;
    const __nv_bfloat16* asrc = g_Ap + (size_t)(m0 + lrow) * KSPLIT + lofs;
    const __nv_bfloat16* bsrc = g_Bp + (size_t)(n0 + lrow) * KSPLIT + lofs;
    const int sidx = lrow * XROWS + lofs;

    const int a_row = wm * 64 + (lane & 7) + ((lane >> 3) & 1) * 8;
    const int a_col = ((lane >> 4) & 1) * 8;
    const int b_row = wn * 32 + (lane & 7) + ((lane >> 4) & 1) * 8;
    const int b_col = ((lane >> 3) & 1) * 8;
    const uint32_t As0 = smem_u32(&As[0][0]);
    const uint32_t Bs0 = smem_u32(&Bs[0][0]);
    const uint32_t BUFA = XBM * XROWS * 2;
    const uint32_t BUFB = XBN * XROWS * 2;

    uint4 a0v = *(const uint4*)(asrc);
    uint4 a1v = *(const uint4*)(asrc + 8);
    uint4 b0v = *(const uint4*)(bsrc);
    uint4 b1v = *(const uint4*)(bsrc + 8);
    *(uint4*)&As[0][sidx]     = a0v;
    *(uint4*)&As[0][sidx + 8] = a1v;
    *(uint4*)&Bs[0][sidx]     = b0v;
    *(uint4*)&Bs[0][sidx + 8] = b1v;
    __syncthreads();

    int p = 0;
    const int NIT = KSPLIT / XBK;   // 48
    for (int it = 0; it < NIT; ++it) {
        const bool more = (it + 1) < NIT;
        if (more) {
            a0v = *(const uint4*)(asrc + (it + 1) * XBK);
            a1v = *(const uint4*)(asrc + (it + 1) * XBK + 8);
            b0v = *(const uint4*)(bsrc + (it + 1) * XBK);
            b1v = *(const uint4*)(bsrc + (it + 1) * XBK + 8);
        }

#pragma unroll
        for (int k16 = 0; k16 < 2; ++k16) {
            uint32_t af[4][4];
#pragma unroll
            for (int mt = 0; mt < 4; ++mt) {
                uint32_t addr = As0 + p * BUFA
                              + (uint32_t)(((a_row + mt * 16) * XROWS + k16 * 16 + a_col) * 2);
                ldsm_x4(af[mt], addr);
            }
            uint32_t bg2[2][4];
#pragma unroll
            for (int hf = 0; hf < 2; ++hf) {
                uint32_t addr = Bs0 + p * BUFB
                              + (uint32_t)(((b_row + hf * 16) * XROWS + k16 * 16 + b_col) * 2);
                ldsm_x4(bg2[hf], addr);
            }
#pragma unroll
            for (int mt = 0; mt < 4; ++mt)
#pragma unroll
                for (int nt = 0; nt < 4; ++nt)
                    hmma16816(acc[mt][nt], af[mt],
                              bg2[nt >> 1][(nt & 1) * 2], bg2[nt >> 1][(nt & 1) * 2 + 1]);
        }

        if (more) {
            *(uint4*)&As[p ^ 1][sidx]     = a0v;
            *(uint4*)&As[p ^ 1][sidx + 8] = a1v;
            *(uint4*)&Bs[p ^ 1][sidx]     = b0v;
            *(uint4*)&Bs[p ^ 1][sidx + 8] = b1v;
            __syncthreads();
        }
        p ^= 1;
    }

#pragma unroll
    for (int mt = 0; mt < 4; ++mt) {
#pragma unroll
        for (int nt = 0; nt < 4; ++nt) {
            int row = m0 + wm * 64 + mt * 16 + (lane >> 2);
            int cl  = wn * 32 + nt * 8 + (lane & 3) * 2;
            float2 v0 = { acc[mt][nt][0] + bsm[cl], acc[mt][nt][1] + bsm[cl + 1] };
            float2 v1 = { acc[mt][nt][2] + bsm[cl], acc[mt][nt][3] + bsm[cl + 1] };
            *(float2*)&g_Xproj[(size_t)row * N4H + n0 + cl]       = v0;
            *(float2*)&g_Xproj[(size_t)(row + 8) * N4H + n0 + cl] = v1;
        }
    }
}

// ---------------- kernel: persistent recurrence via mma.sync (v11) ----------------
// 128 CTAs x 512 thr. CTA r: jg = r&31 (cols [jg*64,+64) = hid [jg*16,+16)),
// bg = r>>5 (batches [bg*16,+16)); 4 independent 32-CTA domains.
// Warp w (0..15): kq = w>>2 (K quarter of 128), wn = w&3 (cols [wn*16,+16)).
// Per kstep: 4 ldsm.x4 (all frags used) + 6 HMMA; 8 ksteps/warp. K quarters
// reduced via smem. Flag barrier (per-CTA monotone u64, warp-0 polls domain).
#define LS_W 520   // smem row stride (512 + 8 pad) in bf16
#define RED_OFF (2*64*LS_W + 2*16*LS_W)                         // bf16 units
#define LSTM_SMEM_BYTES (RED_OFF * 2 + 3*4*32*8*4 + 2*256*4)    // 166400+12288+2048

__global__ __launch_bounds__(512, 1) void lstm_mma() {
    extern __shared__ __nv_bfloat16 sm[];
    __nv_bfloat16* Wh = sm;                    // [64][LS_W]
    __nv_bfloat16* Wl = Wh + 64 * LS_W;
    __nv_bfloat16* Ah = Wl + 64 * LS_W;        // [16][LS_W]
    __nv_bfloat16* Al = Ah + 16 * LS_W;
    float* red = (float*)(sm + RED_OFF);       // [3][4*32][8]
    unsigned* htile = (unsigned*)(red + 3 * 4 * 32 * 8);   // [256]
    unsigned* ctile = htile + 256;

    const int r    = blockIdx.x;
    const int jg   = r & 31;
    const int bg   = r >> 5;
    const int t    = threadIdx.x;
    const int w    = t >> 5;
    const int lane = t & 31;
    const int kq   = w >> 2;        // K quarter (0..3)
    const int wn   = w & 3;         // col group of 16

    __shared__ unsigned long long sbase;
    if (t == 0) sbase = g_flags[r];

    // stage W^T hi/lo slices once (64 rows x 512 bf16 each)
    for (int idx = t; idx < 64 * 64; idx += 512) {
        int row = idx >> 6, ch = idx & 63;
        uint4 vh = *(const uint4*)&g_Whh[(size_t)(jg * 64 + row) * KDIM + ch * 8];
        uint4 vl = *(const uint4*)&g_Whl[(size_t)(jg * 64 + row) * KDIM + ch * 8];
        *(uint4*)&Wh[row * LS_W + ch * 8] = vh;
        *(uint4*)&Wl[row * LS_W + ch * 8] = vl;
    }
    __syncthreads();
    const unsigned long long base = sbase;

    // ldsm element offsets (validated layout)
    const uint32_t Ah0 = smem_u32(Ah), Al0 = smem_u32(Al);
    const uint32_t Wh0 = smem_u32(Wh), Wl0 = smem_u32(Wl);
    const int kbase = kq * 128;
    const uint32_t aoff = (uint32_t)((((lane & 7) + ((lane >> 3) & 1) * 8) * LS_W
                                      + kbase + ((lane >> 4) & 1) * 8) * 2);
    const uint32_t boff = (uint32_t)(((wn * 16 + (lane & 7) + ((lane >> 4) & 1) * 8) * LS_W
                                      + kbase + ((lane >> 3) & 1) * 8) * 2);

    // epilogue assignment (warps 0-3, kq==0): 2 outputs per lane
    const int qq    = (lane & 3) >> 1;
    const int odd   = lane & 1;
    const int b_l   = (lane >> 2) + odd * 8;
    const int hidA  = wn * 4 + qq;
    const int hidB  = wn * 4 + 2 + qq;
    const int b_g   = bg * 16 + b_l;

    float cstA = 0.0f, cstB = 0.0f;
    float4 xpA, xpB;
    if (w < 4) {
        xpA = __ldg((const float4*)(g_Xproj + (size_t)b_g * N4H + (jg * 16 + hidA) * 4));
        xpB = __ldg((const float4*)(g_Xproj + (size_t)b_g * N4H + (jg * 16 + hidB) * 4));
    }

    for (int step = 0; step < T_STEPS; ++step) {
        float accA[4] = {0.f, 0.f, 0.f, 0.f};
        float accB[4] = {0.f, 0.f, 0.f, 0.f};

        if (step > 0) {
            // ---- stage A (hi/lo): warp w stages batch row w ----
            const unsigned* src = g_hx + (size_t)(step - 1) * HB + (size_t)(bg * 16 + w) * DIMH;
#pragma unroll
            for (int q = 0; q < 4; ++q) {
                uint4 v = __ldcg((const uint4*)(src + q * 128 + lane * 4));
                uint2 hhv, llv;
                hhv.x = (v.x & 0xffffu) | (v.y << 16);
                hhv.y = (v.z & 0xffffu) | (v.w << 16);
                llv.x = (v.x >> 16) | (v.y & 0xffff0000u);
                llv.y = (v.z >> 16) | (v.w & 0xffff0000u);
                *(uint2*)&Ah[w * LS_W + q * 128 + lane * 4] = hhv;
                *(uint2*)&Al[w * LS_W + q * 128 + lane * 4] = llv;
            }
            __syncthreads();

            // ---- 8 ksteps x (4 ldsm + 6 hmma), 3-pass bf16x3 ----
#pragma unroll
            for (int ks = 0; ks < 8; ++ks) {
                const uint32_t kofs = (uint32_t)(ks * 16 * 2);
                uint32_t afh[4], afl[4], bh[4], bl[4];
                ldsm_x4(afh, Ah0 + aoff + kofs);
                ldsm_x4(afl, Al0 + aoff + kofs);
                ldsm_x4(bh,  Wh0 + boff + kofs);
                ldsm_x4(bl,  Wl0 + boff + kofs);
                hmma16816(accA, afh, bh[0], bh[1]);
                hmma16816(accB, afh, bh[2], bh[3]);
                hmma16816(accA, afl, bh[0], bh[1]);
                hmma16816(accB, afl, bh[2], bh[3]);
                hmma16816(accA, afh, bl[0], bl[1]);
                hmma16816(accB, afh, bl[2], bl[3]);
            }

            // K-quarters 1..3 publish partials
            if (kq > 0) {
                float* rd = red + (((size_t)(kq - 1) * 128) + wn * 32 + lane) * 8;
                *(float4*)(rd)     = *(float4*)accA;
                *(float4*)(rd + 4) = *(float4*)accB;
            }
        }
        __syncthreads();

        if (w < 4) {
            if (step > 0) {
#pragma unroll
                for (int p = 0; p < 3; ++p) {
                    const float* rd = red + (((size_t)p * 128) + wn * 32 + lane) * 8;
                    float4 pA = *(const float4*)(rd);
                    float4 pB = *(const float4*)(rd + 4);
                    accA[0] += pA.x; accA[1] += pA.y; accA[2] += pA.z; accA[3] += pA.w;
                    accB[0] += pB.x; accB[1] += pB.y; accB[2] += pB.z; accB[3] += pB.w;
                }
            }
            // gate combine within lane pairs (xor 1)
            float eA0 = __shfl_xor_sync(0xffffffffu, accA[0], 1);
            float eA1 = __shfl_xor_sync(0xffffffffu, accA[1], 1);
            float eA2 = __shfl_xor_sync(0xffffffffu, accA[2], 1);
            float eA3 = __shfl_xor_sync(0xffffffffu, accA[3], 1);
            float eB0 = __shfl_xor_sync(0xffffffffu, accB[0], 1);
            float eB1 = __shfl_xor_sync(0xffffffffu, accB[1], 1);
            float eB2 = __shfl_xor_sync(0xffffffffu, accB[2], 1);
            float eB3 = __shfl_xor_sync(0xffffffffu, accB[3], 1);

            float zfA = (odd ? eA2 : accA[0]) + xpA.x;
            float ziA = (odd ? eA3 : accA[1]) + xpA.y;
            float zgA = (odd ? accA[2] : eA0) + xpA.z;
            float zoA = (odd ? accA[3] : eA1) + xpA.w;
            float zfB = (odd ? eB2 : accB[0]) + xpB.x;
            float ziB = (odd ? eB3 : accB[1]) + xpB.y;
            float zgB = (odd ? accB[2] : eB0) + xpB.z;
            float zoB = (odd ? accB[3] : eB1) + xpB.w;

            cstA = sigf(zfA) * cstA + sigf(ziA) * tanh_(zgA);
            cstB = sigf(zfB) * cstB + sigf(ziB) * tanh_(zgB);
            float hA = sigf(zoA) * tanh_(cstA);
            float hB = sigf(zoB) * tanh_(cstB);

            htile[b_l * 16 + hidA] = pack_hl(hA);
            htile[b_l * 16 + hidB] = pack_hl(hB);
            if (step == T_STEPS - 1) {
                ctile[b_l * 16 + hidA] = pack_hl(cstA);
                ctile[b_l * 16 + hidB] = pack_hl(cstB);
            }
            if (step + 1 < T_STEPS) {
                xpA = __ldg((const float4*)(g_Xproj
                        + ((size_t)(step + 1) * BATCH + b_g) * N4H + (jg * 16 + hidA) * 4));
                xpB = __ldg((const float4*)(g_Xproj
                        + ((size_t)(step + 1) * BATCH + b_g) * N4H + (jg * 16 + hidB) * 4));
            }
        }

        __syncthreads();
        // coalesced h' store: thread t<256 -> (b = t>>4, hid = t&15)
        if (t < 256) {
            g_hx[(size_t)step * HB + (size_t)(bg * 16 + (t >> 4)) * DIMH + jg * 16 + (t & 15)]
                = htile[t];
            if (step == T_STEPS - 1)
                g_cx[(size_t)(bg * 16 + (t >> 4)) * DIMH + jg * 16 + (t & 15)] = ctile[t];
        }

        // ---- flag barrier: publish own flag, warp 0 polls domain's 32 flags ----
        __threadfence();
        __syncthreads();
        if (w == 0) {
            const unsigned long long tgt = base + (unsigned long long)(step + 1);
            if (lane == 0) {
                *(volatile unsigned long long*)&g_flags[r] = tgt;
            }
            volatile unsigned long long* fl = &g_flags[bg * 32 + lane];
            while (!__all_sync(0xffffffffu, *fl >= tgt)) { }
            __threadfence();
        }
        __syncthreads();
    }
}

// ---------------- kernel: emit final output (unpack bf16 hi/lo -> fp32) ----------
__global__ __launch_bounds__(512) void emit_out(float* __restrict__ out, int out_size) {
    const int bx = blockIdx.x;        // 0..511: step t; 512: hx tail; 513: cx tail
    const int i4 = blockIdx.y * 512 + threadIdx.x;
    const size_t tail = (size_t)T_STEPS * HB;
    const bool write_state = (size_t)out_size >= tail + 2u * HB;

    const unsigned* src;
    float* dst;
    if (bx < T_STEPS) {
        src = g_hx + (size_t)bx * HB;
        dst = out + (size_t)bx * HB;
    } else if (bx == T_STEPS) {
        if (!write_state) return;
        src = g_hx + (size_t)(T_STEPS - 1) * HB;
        dst = out + tail;
    } else {
        if (!write_state) return;
        src = g_cx;
        dst = out + tail + HB;
    }
    uint4 v = *(const uint4*)(src + (size_t)i4 * 4);
    float4 o;
    o.x = unpack_hl(v.x);
    o.y = unpack_hl(v.y);
    o.z = unpack_hl(v.z);
    o.w = unpack_hl(v.w);
    *(float4*)(dst + (size_t)i4 * 4) = o;
}

// ---------------- launch ----------------------------------------------------------
extern "C" void kernel_launch(void* const* d_in, const int* in_sizes, int n_in,
                              void* d_out, int out_size) {
    const float* inputs = (const float*)d_in[0];
    const float* Wf = (const float*)d_in[1];
    const float* bf = (const float*)d_in[2];
    const float* Wi = (const float*)d_in[3];
    const float* bi = (const float*)d_in[4];
    const float* Wg = (const float*)d_in[5];
    const float* bg = (const float*)d_in[6];
    const float* Wo = (const float*)d_in[7];
    const float* bo = (const float*)d_in[8];

    pack_a<<<1024, 256>>>(inputs);
    pack_b<<<256, 256>>>(Wf, Wi, Wg, Wo);

    dim3 gx(N4H / XBN, MROWS / XBM);   // (16, 256)
    xproj_mma<<<gx, 256>>>(bf, bi, bg, bo);

    cudaFuncSetAttribute(lstm_mma, cudaFuncAttributeMaxDynamicSharedMemorySize, LSTM_SMEM_BYTES);
    lstm_mma<<<128, 512, LSTM_SMEM_BYTES>>>();

    emit_out<<<dim3(T_STEPS + 2, HB / 2048), 512>>>((float*)d_out, out_size);
}

// round 13
// speedup vs baseline: 1.3918x; 1.3918x over previous
#include <cuda_runtime.h>
#include <cuda_bf16.h>
#include <cstdint>
#include <cstddef>

#define T_STEPS 512
#define BATCH   64
#define DIMD    512
#define DIMH    512
#define N4H     2048   // 4 gates * H, packed as j' = hid*4 + gate
#define KDIM    512
#define HB      (DIMH * BATCH)      // 32768
#define MROWS   (T_STEPS * BATCH)   // 32768
#define KSPLIT  1536                // 3 * 512 (bf16x3 split segments)

// ---------------- device scratch (static) ----------------------------------------
__device__ float g_Xproj[(size_t)T_STEPS * BATCH * N4H];   // 256 MB [t*B+b][j']
__device__ unsigned g_hx[(size_t)T_STEPS * HB];            // 64 MB [t][b][hid] packed (hi|lo)
__device__ unsigned g_cx[HB];                              // final c packed [b][hid]
__device__ __nv_bfloat16 g_Ap[(size_t)MROWS * KSPLIT];     // 96 MB  A' = [hi | lo | hi]
__device__ __nv_bfloat16 g_Bp[(size_t)N4H * KSPLIT];       // 6 MB   B'[j'][k] = [hi | hi | lo]
__device__ __nv_bfloat16 g_Whh[(size_t)N4H * KDIM];        // 2 MB   Wh^T hi [j'][k]
__device__ __nv_bfloat16 g_Whl[(size_t)N4H * KDIM];        // 2 MB   Wh^T lo [j'][k]
__device__ unsigned long long g_tickd[2 * 16];             // per-domain tickets (128B apart)
__device__ volatile unsigned long long g_reld[2 * 16];     // per-domain releases

// ---------------- helpers ----------------------------------------------------------
static __device__ __forceinline__ float sigf(float x) {
    return __fdividef(1.0f, 1.0f + __expf(-x));
}
static __device__ __forceinline__ float tanh_(float x) {
    return 2.0f * sigf(2.0f * x) - 1.0f;
}
static __device__ __forceinline__ unsigned pack_hl(float v) {
    __nv_bfloat16 hb = __float2bfloat16(v);
    __nv_bfloat16 lb = __float2bfloat16(v - __bfloat162float(hb));
    return (unsigned)__bfloat16_as_ushort(hb) | ((unsigned)__bfloat16_as_ushort(lb) << 16);
}
static __device__ __forceinline__ float unpack_hl(unsigned u) {
    return __bfloat162float(__ushort_as_bfloat16((unsigned short)(u & 0xffffu)))
         + __bfloat162float(__ushort_as_bfloat16((unsigned short)(u >> 16)));
}
static __device__ __forceinline__ uint32_t smem_u32(const void* p) {
    uint32_t a;
    asm("{ .reg .u64 t; cvta.to.shared.u64 t, %1; cvt.u32.u64 %0, t; }" : "=r"(a) : "l"(p));
    return a;
}
static __device__ __forceinline__ void ldsm_x4(uint32_t* r, uint32_t addr) {
    asm volatile("ldmatrix.sync.aligned.m8n8.x4.shared.b16 {%0,%1,%2,%3}, [%4];"
                 : "=r"(r[0]), "=r"(r[1]), "=r"(r[2]), "=r"(r[3]) : "r"(addr));
}
static __device__ __forceinline__ void hmma16816(float* c, const uint32_t* a,
                                                 uint32_t b0, uint32_t b1) {
    asm volatile("mma.sync.aligned.m16n8k16.row.col.f32.bf16.bf16.f32 "
                 "{%0,%1,%2,%3}, {%4,%5,%6,%7}, {%8,%9}, {%0,%1,%2,%3};"
                 : "+f"(c[0]), "+f"(c[1]), "+f"(c[2]), "+f"(c[3])
                 : "r"(a[0]), "r"(a[1]), "r"(a[2]), "r"(a[3]), "r"(b0), "r"(b1));
}

// ---------------- pack kernels (bf16 hi/lo split) ---------------------------------
__global__ void pack_a(const float* __restrict__ X) {
    size_t idx = (size_t)blockIdx.x * blockDim.x + threadIdx.x;
    size_t stride = (size_t)gridDim.x * blockDim.x;
    for (size_t i = idx; i < (size_t)MROWS * KDIM; i += stride) {
        size_t m = i / KDIM, k = i % KDIM;
        float x = X[i];
        __nv_bfloat16 hi = __float2bfloat16(x);
        __nv_bfloat16 lo = __float2bfloat16(x - __bfloat162float(hi));
        __nv_bfloat16* row = g_Ap + m * KSPLIT;
        row[k] = hi; row[512 + k] = lo; row[1024 + k] = hi;
    }
}
__global__ void pack_b(const float* __restrict__ Wf, const float* __restrict__ Wi,
                       const float* __restrict__ Wg, const float* __restrict__ Wo) {
    size_t idx = (size_t)blockIdx.x * blockDim.x + threadIdx.x;
    size_t stride = (size_t)gridDim.x * blockDim.x;
    for (size_t i = idx; i < (size_t)N4H * KDIM; i += stride) {
        size_t j = i / KDIM, k = i % KDIM;
        int g = (int)(j & 3), c = (int)(j >> 2);
        const float* W = (g == 0) ? Wf : (g == 1) ? Wi : (g == 2) ? Wg : Wo;
        float w = W[k * DIMH + c];
        __nv_bfloat16 hi = __float2bfloat16(w);
        __nv_bfloat16 lo = __float2bfloat16(w - __bfloat162float(hi));
        __nv_bfloat16* row = g_Bp + j * KSPLIT;
        row[k] = hi; row[512 + k] = hi; row[1024 + k] = lo;
        float wh = W[(size_t)(DIMD + k) * DIMH + c];
        __nv_bfloat16 hh = __float2bfloat16(wh);
        __nv_bfloat16 hl = __float2bfloat16(wh - __bfloat162float(hh));
        g_Whh[j * KDIM + k] = hh;
        g_Whl[j * KDIM + k] = hl;
    }
}

// ---------------- kernel: xproj GEMM via mma.sync (bf16x3, fp32 accum) ------------
#define XBM 128
#define XBN 128
#define XBK 32
#define XROWS 40

__global__ __launch_bounds__(256) void xproj_mma(
        const float* __restrict__ bf, const float* __restrict__ bi,
        const float* __restrict__ bg, const float* __restrict__ bo) {
    __shared__ __nv_bfloat16 As[2][XBM * XROWS];
    __shared__ __nv_bfloat16 Bs[2][XBN * XROWS];
    __shared__ float bsm[XBN];

    const int tid  = threadIdx.x;
    const int lane = tid & 31;
    const int wid  = tid >> 5;
    const int wm   = wid & 1;
    const int wn   = wid >> 1;
    const int m0   = blockIdx.y * XBM;
    const int n0   = blockIdx.x * XBN;

    if (tid < XBN) {
        int j = n0 + tid, g = j & 3, c = j >> 2;
        bsm[tid] = (g == 0 ? bf : g == 1 ? bi : g == 2 ? bg : bo)[c];
    }

    float acc[4][4][4];
#pragma unroll
    for (int a = 0; a < 4; ++a)
#pragma unroll
        for (int b = 0; b < 4; ++b)
#pragma unroll
            for (int q = 0; q < 4; ++q) acc[a][b][q] = 0.0f;

    const int lrow = tid >> 1;
    const int lofs = (tid & 1) * 16;
    const __nv_bfloat16* asrc = g_Ap + (size_t)(m0 + lrow) * KSPLIT + lofs;
    const __nv_bfloat16* bsrc = g_Bp + (size_t)(n0 + lrow) * KSPLIT + lofs;
    const int sidx = lrow * XROWS + lofs;

    const int a_row = wm * 64 + (lane & 7) + ((lane >> 3) & 1) * 8;
    const int a_col = ((lane >> 4) & 1) * 8;
    const int b_row = wn * 32 + (lane & 7) + ((lane >> 4) & 1) * 8;
    const int b_col = ((lane >> 3) & 1) * 8;
    const uint32_t As0 = smem_u32(&As[0][0]);
    const uint32_t Bs0 = smem_u32(&Bs[0][0]);
    const uint32_t BUFA = XBM * XROWS * 2;
    const uint32_t BUFB = XBN * XROWS * 2;

    uint4 a0v = *(const uint4*)(asrc);
    uint4 a1v = *(const uint4*)(asrc + 8);
    uint4 b0v = *(const uint4*)(bsrc);
    uint4 b1v = *(const uint4*)(bsrc + 8);
    *(uint4*)&As[0][sidx]     = a0v;
    *(uint4*)&As[0][sidx + 8] = a1v;
    *(uint4*)&Bs[0][sidx]     = b0v;
    *(uint4*)&Bs[0][sidx + 8] = b1v;
    __syncthreads();

    int p = 0;
    const int NIT = KSPLIT / XBK;   // 48
    for (int it = 0; it < NIT; ++it) {
        const bool more = (it + 1) < NIT;
        if (more) {
            a0v = *(const uint4*)(asrc + (it + 1) * XBK);
            a1v = *(const uint4*)(asrc + (it + 1) * XBK + 8);
            b0v = *(const uint4*)(bsrc + (it + 1) * XBK);
            b1v = *(const uint4*)(bsrc + (it + 1) * XBK + 8);
        }

#pragma unroll
        for (int k16 = 0; k16 < 2; ++k16) {
            uint32_t af[4][4];
#pragma unroll
            for (int mt = 0; mt < 4; ++mt) {
                uint32_t addr = As0 + p * BUFA
                              + (uint32_t)(((a_row + mt * 16) * XROWS + k16 * 16 + a_col) * 2);
                ldsm_x4(af[mt], addr);
            }
            uint32_t bg2[2][4];
#pragma unroll
            for (int hf = 0; hf < 2; ++hf) {
                uint32_t addr = Bs0 + p * BUFB
                              + (uint32_t)(((b_row + hf * 16) * XROWS + k16 * 16 + b_col) * 2);
                ldsm_x4(bg2[hf], addr);
            }
#pragma unroll
            for (int mt = 0; mt < 4; ++mt)
#pragma unroll
                for (int nt = 0; nt < 4; ++nt)
                    hmma16816(acc[mt][nt], af[mt],
                              bg2[nt >> 1][(nt & 1) * 2], bg2[nt >> 1][(nt & 1) * 2 + 1]);
        }

        if (more) {
            *(uint4*)&As[p ^ 1][sidx]     = a0v;
            *(uint4*)&As[p ^ 1][sidx + 8] = a1v;
            *(uint4*)&Bs[p ^ 1][sidx]     = b0v;
            *(uint4*)&Bs[p ^ 1][sidx + 8] = b1v;
            __syncthreads();
        }
        p ^= 1;
    }

#pragma unroll
    for (int mt = 0; mt < 4; ++mt) {
#pragma unroll
        for (int nt = 0; nt < 4; ++nt) {
            int row = m0 + wm * 64 + mt * 16 + (lane >> 2);
            int cl  = wn * 32 + nt * 8 + (lane & 3) * 2;
            float2 v0 = { acc[mt][nt][0] + bsm[cl], acc[mt][nt][1] + bsm[cl + 1] };
            float2 v1 = { acc[mt][nt][2] + bsm[cl], acc[mt][nt][3] + bsm[cl + 1] };
            *(float2*)&g_Xproj[(size_t)row * N4H + n0 + cl]       = v0;
            *(float2*)&g_Xproj[(size_t)(row + 8) * N4H + n0 + cl] = v1;
        }
    }
}

// ---------------- kernel: persistent recurrence via mma.sync (v13) ----------------
// 64 CTAs x 256 thr. CTA r: jg = r&31 (cols [jg*64,+64) = hid [jg*16,+16)),
// bg = r>>5 (batches [bg*32,+32)); 2 independent 32-CTA domains.
// Warp w: wm = w>>2 (batch half of 16), wn = w&3 (cols [wn*16,+16)).
// FULL K per warp (32 ksteps x 4 ldsm + 6 hmma) -> NO cross-warp reduce, and
// ALL 8 warps run the epilogue. Atomic ticket barrier per domain (proven).
#define LS_W 520   // smem row stride (512 + 8 pad) in bf16
#define LSTM_SMEM_BYTES ((2*64*LS_W + 2*32*LS_W) * 2 + 2*512*4)  // 199680 + 4096

__global__ __launch_bounds__(256, 1) void lstm_mma() {
    extern __shared__ __nv_bfloat16 sm[];
    __nv_bfloat16* Wh = sm;                    // [64][LS_W]
    __nv_bfloat16* Wl = Wh + 64 * LS_W;
    __nv_bfloat16* Ah = Wl + 64 * LS_W;        // [32][LS_W]
    __nv_bfloat16* Al = Ah + 32 * LS_W;
    unsigned* htile = (unsigned*)(Al + 32 * LS_W);   // [32*16]
    unsigned* ctile = htile + 512;

    const int r    = blockIdx.x;
    const int jg   = r & 31;
    const int bg   = r >> 5;        // 0/1
    const int t    = threadIdx.x;
    const int w    = t >> 5;
    const int lane = t & 31;
    const int wm   = w >> 2;        // batch half (0/1)
    const int wn   = w & 3;         // col group of 16

    // stage W^T hi/lo slices once (64 rows x 512 bf16 each)
    for (int idx = t; idx < 64 * 64; idx += 256) {
        int row = idx >> 6, ch = idx & 63;
        uint4 vh = *(const uint4*)&g_Whh[(size_t)(jg * 64 + row) * KDIM + ch * 8];
        uint4 vl = *(const uint4*)&g_Whl[(size_t)(jg * 64 + row) * KDIM + ch * 8];
        *(uint4*)&Wh[row * LS_W + ch * 8] = vh;
        *(uint4*)&Wl[row * LS_W + ch * 8] = vl;
    }
    __syncthreads();

    // ldsm element offsets (validated layout; A rows = batch-local 0..31)
    const uint32_t Ah0 = smem_u32(Ah), Al0 = smem_u32(Al);
    const uint32_t Wh0 = smem_u32(Wh), Wl0 = smem_u32(Wl);
    const uint32_t aoff = (uint32_t)(((wm * 16 + (lane & 7) + ((lane >> 3) & 1) * 8) * LS_W
                                      + ((lane >> 4) & 1) * 8) * 2);
    const uint32_t boff = (uint32_t)(((wn * 16 + (lane & 7) + ((lane >> 4) & 1) * 8) * LS_W
                                      + ((lane >> 3) & 1) * 8) * 2);

    // epilogue assignment (all warps): 2 outputs per lane
    const int qq    = (lane & 3) >> 1;
    const int odd   = lane & 1;
    const int b_l   = (lane >> 2) + odd * 8;         // 0..15 within wm half
    const int b_loc = wm * 16 + b_l;                 // 0..31 CTA-local batch
    const int hidA  = wn * 4 + qq;
    const int hidB  = wn * 4 + 2 + qq;
    const int b_g   = bg * 32 + b_loc;

    float cstA = 0.0f, cstB = 0.0f;
    float4 xpA = __ldg((const float4*)(g_Xproj + (size_t)b_g * N4H + (jg * 16 + hidA) * 4));
    float4 xpB = __ldg((const float4*)(g_Xproj + (size_t)b_g * N4H + (jg * 16 + hidB) * 4));

    for (int step = 0; step < T_STEPS; ++step) {
        float accA[4] = {0.f, 0.f, 0.f, 0.f};
        float accB[4] = {0.f, 0.f, 0.f, 0.f};

        if (step > 0) {
            // ---- stage A (hi/lo): warp w stages batch rows w*4..w*4+3 ----
            const unsigned* src = g_hx + (size_t)(step - 1) * HB + (size_t)(bg * 32) * DIMH;
#pragma unroll
            for (int bb = 0; bb < 4; ++bb) {
                int brow = w * 4 + bb;
#pragma unroll
                for (int q = 0; q < 4; ++q) {
                    uint4 v = __ldcg((const uint4*)(src + (size_t)brow * DIMH + q * 128 + lane * 4));
                    uint2 hhv, llv;
                    hhv.x = (v.x & 0xffffu) | (v.y << 16);
                    hhv.y = (v.z & 0xffffu) | (v.w << 16);
                    llv.x = (v.x >> 16) | (v.y & 0xffff0000u);
                    llv.y = (v.z >> 16) | (v.w & 0xffff0000u);
                    *(uint2*)&Ah[brow * LS_W + q * 128 + lane * 4] = hhv;
                    *(uint2*)&Al[brow * LS_W + q * 128 + lane * 4] = llv;
                }
            }
            __syncthreads();

            // ---- full K: 32 ksteps x (4 ldsm + 6 hmma), 3-pass bf16x3 ----
#pragma unroll
            for (int ks = 0; ks < 32; ++ks) {
                const uint32_t kofs = (uint32_t)(ks * 16 * 2);
                uint32_t afh[4], afl[4], bh[4], bl[4];
                ldsm_x4(afh, Ah0 + aoff + kofs);
                ldsm_x4(afl, Al0 + aoff + kofs);
                ldsm_x4(bh,  Wh0 + boff + kofs);
                ldsm_x4(bl,  Wl0 + boff + kofs);
                hmma16816(accA, afh, bh[0], bh[1]);
                hmma16816(accB, afh, bh[2], bh[3]);
                hmma16816(accA, afl, bh[0], bh[1]);
                hmma16816(accB, afl, bh[2], bh[3]);
                hmma16816(accA, afh, bl[0], bl[1]);
                hmma16816(accB, afh, bl[2], bl[3]);
            }
        }

        // ---- epilogue on ALL warps (each owns its full-K accumulators) ----
        {
            float eA0 = __shfl_xor_sync(0xffffffffu, accA[0], 1);
            float eA1 = __shfl_xor_sync(0xffffffffu, accA[1], 1);
            float eA2 = __shfl_xor_sync(0xffffffffu, accA[2], 1);
            float eA3 = __shfl_xor_sync(0xffffffffu, accA[3], 1);
            float eB0 = __shfl_xor_sync(0xffffffffu, accB[0], 1);
            float eB1 = __shfl_xor_sync(0xffffffffu, accB[1], 1);
            float eB2 = __shfl_xor_sync(0xffffffffu, accB[2], 1);
            float eB3 = __shfl_xor_sync(0xffffffffu, accB[3], 1);

            float zfA = (odd ? eA2 : accA[0]) + xpA.x;
            float ziA = (odd ? eA3 : accA[1]) + xpA.y;
            float zgA = (odd ? accA[2] : eA0) + xpA.z;
            float zoA = (odd ? accA[3] : eA1) + xpA.w;
            float zfB = (odd ? eB2 : accB[0]) + xpB.x;
            float ziB = (odd ? eB3 : accB[1]) + xpB.y;
            float zgB = (odd ? accB[2] : eB0) + xpB.z;
            float zoB = (odd ? accB[3] : eB1) + xpB.w;

            cstA = sigf(zfA) * cstA + sigf(ziA) * tanh_(zgA);
            cstB = sigf(zfB) * cstB + sigf(ziB) * tanh_(zgB);
            float hA = sigf(zoA) * tanh_(cstA);
            float hB = sigf(zoB) * tanh_(cstB);

            htile[b_loc * 16 + hidA] = pack_hl(hA);
            htile[b_loc * 16 + hidB] = pack_hl(hB);
            if (step == T_STEPS - 1) {
                ctile[b_loc * 16 + hidA] = pack_hl(cstA);
                ctile[b_loc * 16 + hidB] = pack_hl(cstB);
            }
            if (step + 1 < T_STEPS) {
                xpA = __ldg((const float4*)(g_Xproj
                        + ((size_t)(step + 1) * BATCH + b_g) * N4H + (jg * 16 + hidA) * 4));
                xpB = __ldg((const float4*)(g_Xproj
                        + ((size_t)(step + 1) * BATCH + b_g) * N4H + (jg * 16 + hidB) * 4));
            }
        }

        __syncthreads();
        // coalesced h' store: thread t -> 2 entries (b = i>>4, hid = i&15)
#pragma unroll
        for (int rp = 0; rp < 2; ++rp) {
            int i = t + rp * 256;
            g_hx[(size_t)step * HB + (size_t)(bg * 32 + (i >> 4)) * DIMH + jg * 16 + (i & 15)]
                = htile[i];
            if (step == T_STEPS - 1)
                g_cx[(size_t)(bg * 32 + (i >> 4)) * DIMH + jg * 16 + (i & 15)] = ctile[i];
        }

        // ---- per-domain atomic ticket barrier (proven) ----
        __threadfence();
        __syncthreads();
        if (t == 0) {
            unsigned long long tk = atomicAdd(&g_tickd[bg * 16], 1ULL);
            unsigned long long gen = tk >> 5;
            if ((tk & 31ULL) == 31ULL) {
                __threadfence();
                g_reld[bg * 16] = gen + 1ULL;
            } else {
                while (g_reld[bg * 16] <= gen) { }
                __threadfence();
            }
        }
        __syncthreads();
    }
}

// ---------------- kernel: emit final output (unpack bf16 hi/lo -> fp32) ----------
__global__ __launch_bounds__(512) void emit_out(float* __restrict__ out, int out_size) {
    const int bx = blockIdx.x;        // 0..511: step t; 512: hx tail; 513: cx tail
    const int i4 = blockIdx.y * 512 + threadIdx.x;
    const size_t tail = (size_t)T_STEPS * HB;
    const bool write_state = (size_t)out_size >= tail + 2u * HB;

    const unsigned* src;
    float* dst;
    if (bx < T_STEPS) {
        src = g_hx + (size_t)bx * HB;
        dst = out + (size_t)bx * HB;
    } else if (bx == T_STEPS) {
        if (!write_state) return;
        src = g_hx + (size_t)(T_STEPS - 1) * HB;
        dst = out + tail;
    } else {
        if (!write_state) return;
        src = g_cx;
        dst = out + tail + HB;
    }
    uint4 v = *(const uint4*)(src + (size_t)i4 * 4);
    float4 o;
    o.x = unpack_hl(v.x);
    o.y = unpack_hl(v.y);
    o.z = unpack_hl(v.z);
    o.w = unpack_hl(v.w);
    *(float4*)(dst + (size_t)i4 * 4) = o;
}

// ---------------- launch ----------------------------------------------------------
extern "C" void kernel_launch(void* const* d_in, const int* in_sizes, int n_in,
                              void* d_out, int out_size) {
    const float* inputs = (const float*)d_in[0];
    const float* Wf = (const float*)d_in[1];
    const float* bf = (const float*)d_in[2];
    const float* Wi = (const float*)d_in[3];
    const float* bi = (const float*)d_in[4];
    const float* Wg = (const float*)d_in[5];
    const float* bg = (const float*)d_in[6];
    const float* Wo = (const float*)d_in[7];
    const float* bo = (const float*)d_in[8];

    pack_a<<<1024, 256>>>(inputs);
    pack_b<<<256, 256>>>(Wf, Wi, Wg, Wo);

    dim3 gx(N4H / XBN, MROWS / XBM);   // (16, 256)
    xproj_mma<<<gx, 256>>>(bf, bi, bg, bo);

    cudaFuncSetAttribute(lstm_mma, cudaFuncAttributeMaxDynamicSharedMemorySize, LSTM_SMEM_BYTES);
    lstm_mma<<<64, 256, LSTM_SMEM_BYTES>>>();

    emit_out<<<dim3(T_STEPS + 2, HB / 2048), 512>>>((float*)d_out, out_size);
}

// round 14
// speedup vs baseline: 1.6757x; 1.2040x over previous
#include <cuda_runtime.h>
#include <cuda_bf16.h>
#include <cstdint>
#include <cstddef>

#define T_STEPS 512
#define BATCH   64
#define DIMD    512
#define DIMH    512
#define N4H     2048   // 4 gates * H, packed as j' = hid*4 + gate
#define KDIM    512
#define HB      (DIMH * BATCH)      // 32768
#define MROWS   (T_STEPS * BATCH)   // 32768
#define KSPLIT  1536                // 3 * 512 (bf16x3 split segments)

// ---------------- device scratch (static) ----------------------------------------
__device__ float g_Xproj[(size_t)T_STEPS * BATCH * N4H];   // 256 MB [t*B+b][j']
__device__ unsigned g_hx[(size_t)T_STEPS * HB];            // 64 MB [t][b][hid] packed (hi|lo)
__device__ unsigned g_cx[HB];                              // final c packed [b][hid]
__device__ __nv_bfloat16 g_Ap[(size_t)MROWS * KSPLIT];     // 96 MB  A' = [hi | lo | hi]
__device__ __nv_bfloat16 g_Bp[(size_t)N4H * KSPLIT];       // 6 MB   B'[j'][k] = [hi | hi | lo]
__device__ __nv_bfloat16 g_Whh[(size_t)N4H * KDIM];        // 2 MB   Wh^T hi [j'][k]
__device__ __nv_bfloat16 g_Whl[(size_t)N4H * KDIM];        // 2 MB   Wh^T lo [j'][k]
__device__ unsigned long long g_tickd[4 * 16];             // per-domain tickets (128B apart)
__device__ volatile unsigned long long g_reld[4 * 16];     // per-domain releases

// ---------------- helpers ----------------------------------------------------------
static __device__ __forceinline__ float sigf(float x) {
    return __fdividef(1.0f, 1.0f + __expf(-x));
}
static __device__ __forceinline__ float tanh_(float x) {
    return 2.0f * sigf(2.0f * x) - 1.0f;
}
static __device__ __forceinline__ unsigned pack_hl(float v) {
    __nv_bfloat16 hb = __float2bfloat16(v);
    __nv_bfloat16 lb = __float2bfloat16(v - __bfloat162float(hb));
    return (unsigned)__bfloat16_as_ushort(hb) | ((unsigned)__bfloat16_as_ushort(lb) << 16);
}
static __device__ __forceinline__ float unpack_hl(unsigned u) {
    return __bfloat162float(__ushort_as_bfloat16((unsigned short)(u & 0xffffu)))
         + __bfloat162float(__ushort_as_bfloat16((unsigned short)(u >> 16)));
}
static __device__ __forceinline__ uint32_t smem_u32(const void* p) {
    uint32_t a;
    asm("{ .reg .u64 t; cvta.to.shared.u64 t, %1; cvt.u32.u64 %0, t; }" : "=r"(a) : "l"(p));
    return a;
}
static __device__ __forceinline__ void ldsm_x4(uint32_t* r, uint32_t addr) {
    asm volatile("ldmatrix.sync.aligned.m8n8.x4.shared.b16 {%0,%1,%2,%3}, [%4];"
                 : "=r"(r[0]), "=r"(r[1]), "=r"(r[2]), "=r"(r[3]) : "r"(addr));
}
static __device__ __forceinline__ void hmma16816(float* c, const uint32_t* a,
                                                 uint32_t b0, uint32_t b1) {
    asm volatile("mma.sync.aligned.m16n8k16.row.col.f32.bf16.bf16.f32 "
                 "{%0,%1,%2,%3}, {%4,%5,%6,%7}, {%8,%9}, {%0,%1,%2,%3};"
                 : "+f"(c[0]), "+f"(c[1]), "+f"(c[2]), "+f"(c[3])
                 : "r"(a[0]), "r"(a[1]), "r"(a[2]), "r"(a[3]), "r"(b0), "r"(b1));
}

// ---------------- pack kernels (bf16 hi/lo split) ---------------------------------
__global__ void pack_a(const float* __restrict__ X) {
    size_t idx = (size_t)blockIdx.x * blockDim.x + threadIdx.x;
    size_t stride = (size_t)gridDim.x * blockDim.x;
    for (size_t i = idx; i < (size_t)MROWS * KDIM; i += stride) {
        size_t m = i / KDIM, k = i % KDIM;
        float x = X[i];
        __nv_bfloat16 hi = __float2bfloat16(x);
        __nv_bfloat16 lo = __float2bfloat16(x - __bfloat162float(hi));
        __nv_bfloat16* row = g_Ap + m * KSPLIT;
        row[k] = hi; row[512 + k] = lo; row[1024 + k] = hi;
    }
}
__global__ void pack_b(const float* __restrict__ Wf, const float* __restrict__ Wi,
                       const float* __restrict__ Wg, const float* __restrict__ Wo) {
    size_t idx = (size_t)blockIdx.x * blockDim.x + threadIdx.x;
    size_t stride = (size_t)gridDim.x * blockDim.x;
    for (size_t i = idx; i < (size_t)N4H * KDIM; i += stride) {
        size_t j = i / KDIM, k = i % KDIM;
        int g = (int)(j & 3), c = (int)(j >> 2);
        const float* W = (g == 0) ? Wf : (g == 1) ? Wi : (g == 2) ? Wg : Wo;
        float w = W[k * DIMH + c];
        __nv_bfloat16 hi = __float2bfloat16(w);
        __nv_bfloat16 lo = __float2bfloat16(w - __bfloat162float(hi));
        __nv_bfloat16* row = g_Bp + j * KSPLIT;
        row[k] = hi; row[512 + k] = hi; row[1024 + k] = lo;
        float wh = W[(size_t)(DIMD + k) * DIMH + c];
        __nv_bfloat16 hh = __float2bfloat16(wh);
        __nv_bfloat16 hl = __float2bfloat16(wh - __bfloat162float(hh));
        g_Whh[j * KDIM + k] = hh;
        g_Whl[j * KDIM + k] = hl;
    }
}

// ---------------- kernel: xproj GEMM via mma.sync (bf16x3, fp32 accum) ------------
#define XBM 128
#define XBN 128
#define XBK 32
#define XROWS 40

__global__ __launch_bounds__(256) void xproj_mma(
        const float* __restrict__ bf, const float* __restrict__ bi,
        const float* __restrict__ bg, const float* __restrict__ bo) {
    __shared__ __nv_bfloat16 As[2][XBM * XROWS];
    __shared__ __nv_bfloat16 Bs[2][XBN * XROWS];
    __shared__ float bsm[XBN];

    const int tid  = threadIdx.x;
    const int lane = tid & 31;
    const int wid  = tid >> 5;
    const int wm   = wid & 1;
    const int wn   = wid >> 1;
    const int m0   = blockIdx.y * XBM;
    const int n0   = blockIdx.x * XBN;

    if (tid < XBN) {
        int j = n0 + tid, g = j & 3, c = j >> 2;
        bsm[tid] = (g == 0 ? bf : g == 1 ? bi : g == 2 ? bg : bo)[c];
    }

    float acc[4][4][4];
#pragma unroll
    for (int a = 0; a < 4; ++a)
#pragma unroll
        for (int b = 0; b < 4; ++b)
#pragma unroll
            for (int q = 0; q < 4; ++q) acc[a][b][q] = 0.0f;

    const int lrow = tid >> 1;
    const int lofs = (tid & 1) * 16;
    const __nv_bfloat16* asrc = g_Ap + (size_t)(m0 + lrow) * KSPLIT + lofs;
    const __nv_bfloat16* bsrc = g_Bp + (size_t)(n0 + lrow) * KSPLIT + lofs;
    const int sidx = lrow * XROWS + lofs;

    const int a_row = wm * 64 + (lane & 7) + ((lane >> 3) & 1) * 8;
    const int a_col = ((lane >> 4) & 1) * 8;
    const int b_row = wn * 32 + (lane & 7) + ((lane >> 4) & 1) * 8;
    const int b_col = ((lane >> 3) & 1) * 8;
    const uint32_t As0 = smem_u32(&As[0][0]);
    const uint32_t Bs0 = smem_u32(&Bs[0][0]);
    const uint32_t BUFA = XBM * XROWS * 2;
    const uint32_t BUFB = XBN * XROWS * 2;

    uint4 a0v = *(const uint4*)(asrc);
    uint4 a1v = *(const uint4*)(asrc + 8);
    uint4 b0v = *(const uint4*)(bsrc);
    uint4 b1v = *(const uint4*)(bsrc + 8);
    *(uint4*)&As[0][sidx]     = a0v;
    *(uint4*)&As[0][sidx + 8] = a1v;
    *(uint4*)&Bs[0][sidx]     = b0v;
    *(uint4*)&Bs[0][sidx + 8] = b1v;
    __syncthreads();

    int p = 0;
    const int NIT = KSPLIT / XBK;   // 48
    for (int it = 0; it < NIT; ++it) {
        const bool more = (it + 1) < NIT;
        if (more) {
            a0v = *(const uint4*)(asrc + (it + 1) * XBK);
            a1v = *(const uint4*)(asrc + (it + 1) * XBK + 8);
            b0v = *(const uint4*)(bsrc + (it + 1) * XBK);
            b1v = *(const uint4*)(bsrc + (it + 1) * XBK + 8);
        }

#pragma unroll
        for (int k16 = 0; k16 < 2; ++k16) {
            uint32_t af[4][4];
#pragma unroll
            for (int mt = 0; mt < 4; ++mt) {
                uint32_t addr = As0 + p * BUFA
                              + (uint32_t)(((a_row + mt * 16) * XROWS + k16 * 16 + a_col) * 2);
                ldsm_x4(af[mt], addr);
            }
            uint32_t bg2[2][4];
#pragma unroll
            for (int hf = 0; hf < 2; ++hf) {
                uint32_t addr = Bs0 + p * BUFB
                              + (uint32_t)(((b_row + hf * 16) * XROWS + k16 * 16 + b_col) * 2);
                ldsm_x4(bg2[hf], addr);
            }
#pragma unroll
            for (int mt = 0; mt < 4; ++mt)
#pragma unroll
                for (int nt = 0; nt < 4; ++nt)
                    hmma16816(acc[mt][nt], af[mt],
                              bg2[nt >> 1][(nt & 1) * 2], bg2[nt >> 1][(nt & 1) * 2 + 1]);
        }

        if (more) {
            *(uint4*)&As[p ^ 1][sidx]     = a0v;
            *(uint4*)&As[p ^ 1][sidx + 8] = a1v;
            *(uint4*)&Bs[p ^ 1][sidx]     = b0v;
            *(uint4*)&Bs[p ^ 1][sidx + 8] = b1v;
            __syncthreads();
        }
        p ^= 1;
    }

#pragma unroll
    for (int mt = 0; mt < 4; ++mt) {
#pragma unroll
        for (int nt = 0; nt < 4; ++nt) {
            int row = m0 + wm * 64 + mt * 16 + (lane >> 2);
            int cl  = wn * 32 + nt * 8 + (lane & 3) * 2;
            float2 v0 = { acc[mt][nt][0] + bsm[cl], acc[mt][nt][1] + bsm[cl + 1] };
            float2 v1 = { acc[mt][nt][2] + bsm[cl], acc[mt][nt][3] + bsm[cl + 1] };
            *(float2*)&g_Xproj[(size_t)row * N4H + n0 + cl]       = v0;
            *(float2*)&g_Xproj[(size_t)(row + 8) * N4H + n0 + cl] = v1;
        }
    }
}

// ---------------- kernel: persistent recurrence via mma.sync (v14) ----------------
// 128 CTAs x 512 thr. CTA r: jg = r&31 (cols [jg*64,+64) = hid [jg*16,+16)),
// bg = r>>5 (batches [bg*16,+16)); 4 independent 32-CTA domains.
// Warp w (0..15): kq = w>>2 (K quarter of 128), wn = w&3 (cols [wn*16,+16)).
// Per kstep: 4 ldsm.x4 (all frags used) + 6 HMMA; 8 ksteps/warp. K quarters
// reduced via smem. Per-domain ATOMIC TICKET barrier (proven; flags are toxic).
#define LS_W 520   // smem row stride (512 + 8 pad) in bf16
#define RED_OFF (2*64*LS_W + 2*16*LS_W)                         // bf16 units
#define LSTM_SMEM_BYTES (RED_OFF * 2 + 3*4*32*8*4 + 2*256*4)    // 166400+12288+2048

__global__ __launch_bounds__(512, 1) void lstm_mma() {
    extern __shared__ __nv_bfloat16 sm[];
    __nv_bfloat16* Wh = sm;                    // [64][LS_W]
    __nv_bfloat16* Wl = Wh + 64 * LS_W;
    __nv_bfloat16* Ah = Wl + 64 * LS_W;        // [16][LS_W]
    __nv_bfloat16* Al = Ah + 16 * LS_W;
    float* red = (float*)(sm + RED_OFF);       // [3][4*32][8]
    unsigned* htile = (unsigned*)(red + 3 * 4 * 32 * 8);   // [256]
    unsigned* ctile = htile + 256;

    const int r    = blockIdx.x;
    const int jg   = r & 31;
    const int bg   = r >> 5;
    const int t    = threadIdx.x;
    const int w    = t >> 5;
    const int lane = t & 31;
    const int kq   = w >> 2;        // K quarter (0..3)
    const int wn   = w & 3;         // col group of 16

    // stage W^T hi/lo slices once (64 rows x 512 bf16 each)
    for (int idx = t; idx < 64 * 64; idx += 512) {
        int row = idx >> 6, ch = idx & 63;
        uint4 vh = *(const uint4*)&g_Whh[(size_t)(jg * 64 + row) * KDIM + ch * 8];
        uint4 vl = *(const uint4*)&g_Whl[(size_t)(jg * 64 + row) * KDIM + ch * 8];
        *(uint4*)&Wh[row * LS_W + ch * 8] = vh;
        *(uint4*)&Wl[row * LS_W + ch * 8] = vl;
    }
    __syncthreads();

    // ldsm element offsets (validated layout)
    const uint32_t Ah0 = smem_u32(Ah), Al0 = smem_u32(Al);
    const uint32_t Wh0 = smem_u32(Wh), Wl0 = smem_u32(Wl);
    const int kbase = kq * 128;
    const uint32_t aoff = (uint32_t)((((lane & 7) + ((lane >> 3) & 1) * 8) * LS_W
                                      + kbase + ((lane >> 4) & 1) * 8) * 2);
    const uint32_t boff = (uint32_t)(((wn * 16 + (lane & 7) + ((lane >> 4) & 1) * 8) * LS_W
                                      + kbase + ((lane >> 3) & 1) * 8) * 2);

    // epilogue assignment (warps 0-3, kq==0): 2 outputs per lane
    const int qq    = (lane & 3) >> 1;
    const int odd   = lane & 1;
    const int b_l   = (lane >> 2) + odd * 8;
    const int hidA  = wn * 4 + qq;
    const int hidB  = wn * 4 + 2 + qq;
    const int b_g   = bg * 16 + b_l;

    float cstA = 0.0f, cstB = 0.0f;
    float4 xpA, xpB;
    if (w < 4) {
        xpA = __ldg((const float4*)(g_Xproj + (size_t)b_g * N4H + (jg * 16 + hidA) * 4));
        xpB = __ldg((const float4*)(g_Xproj + (size_t)b_g * N4H + (jg * 16 + hidB) * 4));
    }

    for (int step = 0; step < T_STEPS; ++step) {
        float accA[4] = {0.f, 0.f, 0.f, 0.f};
        float accB[4] = {0.f, 0.f, 0.f, 0.f};

        if (step > 0) {
            // ---- stage A (hi/lo): warp w stages batch row w ----
            const unsigned* src = g_hx + (size_t)(step - 1) * HB + (size_t)(bg * 16 + w) * DIMH;
#pragma unroll
            for (int q = 0; q < 4; ++q) {
                uint4 v = __ldcg((const uint4*)(src + q * 128 + lane * 4));
                uint2 hhv, llv;
                hhv.x = (v.x & 0xffffu) | (v.y << 16);
                hhv.y = (v.z & 0xffffu) | (v.w << 16);
                llv.x = (v.x >> 16) | (v.y & 0xffff0000u);
                llv.y = (v.z >> 16) | (v.w & 0xffff0000u);
                *(uint2*)&Ah[w * LS_W + q * 128 + lane * 4] = hhv;
                *(uint2*)&Al[w * LS_W + q * 128 + lane * 4] = llv;
            }
            __syncthreads();

            // ---- 8 ksteps x (4 ldsm + 6 hmma), 3-pass bf16x3 ----
#pragma unroll
            for (int ks = 0; ks < 8; ++ks) {
                const uint32_t kofs = (uint32_t)(ks * 16 * 2);
                uint32_t afh[4], afl[4], bh[4], bl[4];
                ldsm_x4(afh, Ah0 + aoff + kofs);
                ldsm_x4(afl, Al0 + aoff + kofs);
                ldsm_x4(bh,  Wh0 + boff + kofs);
                ldsm_x4(bl,  Wl0 + boff + kofs);
                hmma16816(accA, afh, bh[0], bh[1]);
                hmma16816(accB, afh, bh[2], bh[3]);
                hmma16816(accA, afl, bh[0], bh[1]);
                hmma16816(accB, afl, bh[2], bh[3]);
                hmma16816(accA, afh, bl[0], bl[1]);
                hmma16816(accB, afh, bl[2], bl[3]);
            }

            // K-quarters 1..3 publish partials
            if (kq > 0) {
                float* rd = red + (((size_t)(kq - 1) * 128) + wn * 32 + lane) * 8;
                *(float4*)(rd)     = *(float4*)accA;
                *(float4*)(rd + 4) = *(float4*)accB;
            }
        }
        __syncthreads();

        if (w < 4) {
            if (step > 0) {
#pragma unroll
                for (int p = 0; p < 3; ++p) {
                    const float* rd = red + (((size_t)p * 128) + wn * 32 + lane) * 8;
                    float4 pA = *(const float4*)(rd);
                    float4 pB = *(const float4*)(rd + 4);
                    accA[0] += pA.x; accA[1] += pA.y; accA[2] += pA.z; accA[3] += pA.w;
                    accB[0] += pB.x; accB[1] += pB.y; accB[2] += pB.z; accB[3] += pB.w;
                }
            }
            // gate combine within lane pairs (xor 1)
            float eA0 = __shfl_xor_sync(0xffffffffu, accA[0], 1);
            float eA1 = __shfl_xor_sync(0xffffffffu, accA[1], 1);
            float eA2 = __shfl_xor_sync(0xffffffffu, accA[2], 1);
            float eA3 = __shfl_xor_sync(0xffffffffu, accA[3], 1);
            float eB0 = __shfl_xor_sync(0xffffffffu, accB[0], 1);
            float eB1 = __shfl_xor_sync(0xffffffffu, accB[1], 1);
            float eB2 = __shfl_xor_sync(0xffffffffu, accB[2], 1);
            float eB3 = __shfl_xor_sync(0xffffffffu, accB[3], 1);

            float zfA = (odd ? eA2 : accA[0]) + xpA.x;
            float ziA = (odd ? eA3 : accA[1]) + xpA.y;
            float zgA = (odd ? accA[2] : eA0) + xpA.z;
            float zoA = (odd ? accA[3] : eA1) + xpA.w;
            float zfB = (odd ? eB2 : accB[0]) + xpB.x;
            float ziB = (odd ? eB3 : accB[1]) + xpB.y;
            float zgB = (odd ? accB[2] : eB0) + xpB.z;
            float zoB = (odd ? accB[3] : eB1) + xpB.w;

            cstA = sigf(zfA) * cstA + sigf(ziA) * tanh_(zgA);
            cstB = sigf(zfB) * cstB + sigf(ziB) * tanh_(zgB);
            float hA = sigf(zoA) * tanh_(cstA);
            float hB = sigf(zoB) * tanh_(cstB);

            htile[b_l * 16 + hidA] = pack_hl(hA);
            htile[b_l * 16 + hidB] = pack_hl(hB);
            if (step == T_STEPS - 1) {
                ctile[b_l * 16 + hidA] = pack_hl(cstA);
                ctile[b_l * 16 + hidB] = pack_hl(cstB);
            }
            if (step + 1 < T_STEPS) {
                xpA = __ldg((const float4*)(g_Xproj
                        + ((size_t)(step + 1) * BATCH + b_g) * N4H + (jg * 16 + hidA) * 4));
                xpB = __ldg((const float4*)(g_Xproj
                        + ((size_t)(step + 1) * BATCH + b_g) * N4H + (jg * 16 + hidB) * 4));
            }
        }

        __syncthreads();
        // coalesced h' store: thread t<256 -> (b = t>>4, hid = t&15)
        if (t < 256) {
            g_hx[(size_t)step * HB + (size_t)(bg * 16 + (t >> 4)) * DIMH + jg * 16 + (t & 15)]
                = htile[t];
            if (step == T_STEPS - 1)
                g_cx[(size_t)(bg * 16 + (t >> 4)) * DIMH + jg * 16 + (t & 15)] = ctile[t];
        }

        // ---- per-domain atomic ticket barrier (proven; 32 CTAs per domain) ----
        __threadfence();
        __syncthreads();
        if (t == 0) {
            unsigned long long tk = atomicAdd(&g_tickd[bg * 16], 1ULL);
            unsigned long long gen = tk >> 5;
            if ((tk & 31ULL) == 31ULL) {
                __threadfence();
                g_reld[bg * 16] = gen + 1ULL;
            } else {
                while (g_reld[bg * 16] <= gen) { }
                __threadfence();
            }
        }
        __syncthreads();
    }
}

// ---------------- kernel: emit final output (unpack bf16 hi/lo -> fp32) ----------
__global__ __launch_bounds__(512) void emit_out(float* __restrict__ out, int out_size) {
    const int bx = blockIdx.x;        // 0..511: step t; 512: hx tail; 513: cx tail
    const int i4 = blockIdx.y * 512 + threadIdx.x;
    const size_t tail = (size_t)T_STEPS * HB;
    const bool write_state = (size_t)out_size >= tail + 2u * HB;

    const unsigned* src;
    float* dst;
    if (bx < T_STEPS) {
        src = g_hx + (size_t)bx * HB;
        dst = out + (size_t)bx * HB;
    } else if (bx == T_STEPS) {
        if (!write_state) return;
        src = g_hx + (size_t)(T_STEPS - 1) * HB;
        dst = out + tail;
    } else {
        if (!write_state) return;
        src = g_cx;
        dst = out + tail + HB;
    }
    uint4 v = *(const uint4*)(src + (size_t)i4 * 4);
    float4 o;
    o.x = unpack_hl(v.x);
    o.y = unpack_hl(v.y);
    o.z = unpack_hl(v.z);
    o.w = unpack_hl(v.w);
    *(float4*)(dst + (size_t)i4 * 4) = o;
}

// ---------------- launch ----------------------------------------------------------
extern "C" void kernel_launch(void* const* d_in, const int* in_sizes, int n_in,
                              void* d_out, int out_size) {
    const float* inputs = (const float*)d_in[0];
    const float* Wf = (const float*)d_in[1];
    const float* bf = (const float*)d_in[2];
    const float* Wi = (const float*)d_in[3];
    const float* bi = (const float*)d_in[4];
    const float* Wg = (const float*)d_in[5];
    const float* bg = (const float*)d_in[6];
    const float* Wo = (const float*)d_in[7];
    const float* bo = (const float*)d_in[8];

    pack_a<<<1024, 256>>>(inputs);
    pack_b<<<256, 256>>>(Wf, Wi, Wg, Wo);

    dim3 gx(N4H / XBN, MROWS / XBM);   // (16, 256)
    xproj_mma<<<gx, 256>>>(bf, bi, bg, bo);

    cudaFuncSetAttribute(lstm_mma, cudaFuncAttributeMaxDynamicSharedMemorySize, LSTM_SMEM_BYTES);
    lstm_mma<<<128, 512, LSTM_SMEM_BYTES>>>();

    emit_out<<<dim3(T_STEPS + 2, HB / 2048), 512>>>((float*)d_out, out_size);
}

// round 15
// speedup vs baseline: 1.7349x; 1.0353x over previous
#include <cuda_runtime.h>
#include <cuda_bf16.h>
#include <cstdint>
#include <cstddef>

#define T_STEPS 512
#define BATCH   64
#define DIMD    512
#define DIMH    512
#define N4H     2048   // 4 gates * H, packed as j' = hid*4 + gate
#define KDIM    512
#define HB      (DIMH * BATCH)      // 32768
#define MROWS   (T_STEPS * BATCH)   // 32768
#define KSPLIT  1536                // 3 * 512 (bf16x3 split segments)

// ---------------- device scratch (static) ----------------------------------------
__device__ float g_Xproj[(size_t)T_STEPS * BATCH * N4H];   // 256 MB [t*B+b][j']
__device__ unsigned g_hx[(size_t)T_STEPS * HB];            // 64 MB [t][b][hid] packed (hi|lo)
__device__ unsigned g_cx[HB];                              // final c packed [b][hid]
__device__ __nv_bfloat16 g_Ap[(size_t)MROWS * KSPLIT];     // 96 MB  A' = [hi | lo | hi]
__device__ __nv_bfloat16 g_Bp[(size_t)N4H * KSPLIT];       // 6 MB   B'[j'][k] = [hi | hi | lo]
__device__ __nv_bfloat16 g_Whh[(size_t)N4H * KDIM];        // 2 MB   Wh^T hi [j'][k]
__device__ __nv_bfloat16 g_Whl[(size_t)N4H * KDIM];        // 2 MB   Wh^T lo [j'][k]
__device__ unsigned long long g_tickd[4 * 16];             // per-domain tickets (128B apart)
__device__ volatile unsigned long long g_reld[4 * 16];     // per-domain releases

// ---------------- helpers ----------------------------------------------------------
static __device__ __forceinline__ float sigf(float x) {
    return __fdividef(1.0f, 1.0f + __expf(-x));
}
static __device__ __forceinline__ float tanh_(float x) {
    return 2.0f * sigf(2.0f * x) - 1.0f;
}
static __device__ __forceinline__ unsigned pack_hl(float v) {
    __nv_bfloat16 hb = __float2bfloat16(v);
    __nv_bfloat16 lb = __float2bfloat16(v - __bfloat162float(hb));
    return (unsigned)__bfloat16_as_ushort(hb) | ((unsigned)__bfloat16_as_ushort(lb) << 16);
}
static __device__ __forceinline__ float unpack_hl(unsigned u) {
    return __bfloat162float(__ushort_as_bfloat16((unsigned short)(u & 0xffffu)))
         + __bfloat162float(__ushort_as_bfloat16((unsigned short)(u >> 16)));
}
static __device__ __forceinline__ uint32_t smem_u32(const void* p) {
    uint32_t a;
    asm("{ .reg .u64 t; cvta.to.shared.u64 t, %1; cvt.u32.u64 %0, t; }" : "=r"(a) : "l"(p));
    return a;
}
static __device__ __forceinline__ void ldsm_x4(uint32_t* r, uint32_t addr) {
    asm volatile("ldmatrix.sync.aligned.m8n8.x4.shared.b16 {%0,%1,%2,%3}, [%4];"
                 : "=r"(r[0]), "=r"(r[1]), "=r"(r[2]), "=r"(r[3]) : "r"(addr));
}
static __device__ __forceinline__ void hmma16816(float* c, const uint32_t* a,
                                                 uint32_t b0, uint32_t b1) {
    asm volatile("mma.sync.aligned.m16n8k16.row.col.f32.bf16.bf16.f32 "
                 "{%0,%1,%2,%3}, {%4,%5,%6,%7}, {%8,%9}, {%0,%1,%2,%3};"
                 : "+f"(c[0]), "+f"(c[1]), "+f"(c[2]), "+f"(c[3])
                 : "r"(a[0]), "r"(a[1]), "r"(a[2]), "r"(a[3]), "r"(b0), "r"(b1));
}

// ---------------- pack kernels (bf16 hi/lo split) ---------------------------------
__global__ void pack_a(const float* __restrict__ X) {
    size_t idx = (size_t)blockIdx.x * blockDim.x + threadIdx.x;
    size_t stride = (size_t)gridDim.x * blockDim.x;
    for (size_t i = idx; i < (size_t)MROWS * KDIM; i += stride) {
        size_t m = i / KDIM, k = i % KDIM;
        float x = X[i];
        __nv_bfloat16 hi = __float2bfloat16(x);
        __nv_bfloat16 lo = __float2bfloat16(x - __bfloat162float(hi));
        __nv_bfloat16* row = g_Ap + m * KSPLIT;
        row[k] = hi; row[512 + k] = lo; row[1024 + k] = hi;
    }
}
__global__ void pack_b(const float* __restrict__ Wf, const float* __restrict__ Wi,
                       const float* __restrict__ Wg, const float* __restrict__ Wo) {
    size_t idx = (size_t)blockIdx.x * blockDim.x + threadIdx.x;
    size_t stride = (size_t)gridDim.x * blockDim.x;
    for (size_t i = idx; i < (size_t)N4H * KDIM; i += stride) {
        size_t j = i / KDIM, k = i % KDIM;
        int g = (int)(j & 3), c = (int)(j >> 2);
        const float* W = (g == 0) ? Wf : (g == 1) ? Wi : (g == 2) ? Wg : Wo;
        float w = W[k * DIMH + c];
        __nv_bfloat16 hi = __float2bfloat16(w);
        __nv_bfloat16 lo = __float2bfloat16(w - __bfloat162float(hi));
        __nv_bfloat16* row = g_Bp + j * KSPLIT;
        row[k] = hi; row[512 + k] = hi; row[1024 + k] = lo;
        float wh = W[(size_t)(DIMD + k) * DIMH + c];
        __nv_bfloat16 hh = __float2bfloat16(wh);
        __nv_bfloat16 hl = __float2bfloat16(wh - __bfloat162float(hh));
        g_Whh[j * KDIM + k] = hh;
        g_Whl[j * KDIM + k] = hl;
    }
}

// ---------------- kernel: xproj GEMM via mma.sync (bf16x3, fp32 accum) ------------
#define XBM 128
#define XBN 128
#define XBK 32
#define XROWS 40

__global__ __launch_bounds__(256) void xproj_mma(
        const float* __restrict__ bf, const float* __restrict__ bi,
        const float* __restrict__ bg, const float* __restrict__ bo) {
    __shared__ __nv_bfloat16 As[2][XBM * XROWS];
    __shared__ __nv_bfloat16 Bs[2][XBN * XROWS];
    __shared__ float bsm[XBN];

    const int tid  = threadIdx.x;
    const int lane = tid & 31;
    const int wid  = tid >> 5;
    const int wm   = wid & 1;
    const int wn   = wid >> 1;
    const int m0   = blockIdx.y * XBM;
    const int n0   = blockIdx.x * XBN;

    if (tid < XBN) {
        int j = n0 + tid, g = j & 3, c = j >> 2;
        bsm[tid] = (g == 0 ? bf : g == 1 ? bi : g == 2 ? bg : bo)[c];
    }

    float acc[4][4][4];
#pragma unroll
    for (int a = 0; a < 4; ++a)
#pragma unroll
        for (int b = 0; b < 4; ++b)
#pragma unroll
            for (int q = 0; q < 4; ++q) acc[a][b][q] = 0.0f;

    const int lrow = tid >> 1;
    const int lofs = (tid & 1) * 16;
    const __nv_bfloat16* asrc = g_Ap + (size_t)(m0 + lrow) * KSPLIT + lofs;
    const __nv_bfloat16* bsrc = g_Bp + (size_t)(n0 + lrow) * KSPLIT + lofs;
    const int sidx = lrow * XROWS + lofs;

    const int a_row = wm * 64 + (lane & 7) + ((lane >> 3) & 1) * 8;
    const int a_col = ((lane >> 4) & 1) * 8;
    const int b_row = wn * 32 + (lane & 7) + ((lane >> 4) & 1) * 8;
    const int b_col = ((lane >> 3) & 1) * 8;
    const uint32_t As0 = smem_u32(&As[0][0]);
    const uint32_t Bs0 = smem_u32(&Bs[0][0]);
    const uint32_t BUFA = XBM * XROWS * 2;
    const uint32_t BUFB = XBN * XROWS * 2;

    uint4 a0v = *(const uint4*)(asrc);
    uint4 a1v = *(const uint4*)(asrc + 8);
    uint4 b0v = *(const uint4*)(bsrc);
    uint4 b1v = *(const uint4*)(bsrc + 8);
    *(uint4*)&As[0][sidx]     = a0v;
    *(uint4*)&As[0][sidx + 8] = a1v;
    *(uint4*)&Bs[0][sidx]     = b0v;
    *(uint4*)&Bs[0][sidx + 8] = b1v;
    __syncthreads();

    int p = 0;
    const int NIT = KSPLIT / XBK;   // 48
    for (int it = 0; it < NIT; ++it) {
        const bool more = (it + 1) < NIT;
        if (more) {
            a0v = *(const uint4*)(asrc + (it + 1) * XBK);
            a1v = *(const uint4*)(asrc + (it + 1) * XBK + 8);
            b0v = *(const uint4*)(bsrc + (it + 1) * XBK);
            b1v = *(const uint4*)(bsrc + (it + 1) * XBK + 8);
        }

#pragma unroll
        for (int k16 = 0; k16 < 2; ++k16) {
            uint32_t af[4][4];
#pragma unroll
            for (int mt = 0; mt < 4; ++mt) {
                uint32_t addr = As0 + p * BUFA
                              + (uint32_t)(((a_row + mt * 16) * XROWS + k16 * 16 + a_col) * 2);
                ldsm_x4(af[mt], addr);
            }
            uint32_t bg2[2][4];
#pragma unroll
            for (int hf = 0; hf < 2; ++hf) {
                uint32_t addr = Bs0 + p * BUFB
                              + (uint32_t)(((b_row + hf * 16) * XROWS + k16 * 16 + b_col) * 2);
                ldsm_x4(bg2[hf], addr);
            }
#pragma unroll
            for (int mt = 0; mt < 4; ++mt)
#pragma unroll
                for (int nt = 0; nt < 4; ++nt)
                    hmma16816(acc[mt][nt], af[mt],
                              bg2[nt >> 1][(nt & 1) * 2], bg2[nt >> 1][(nt & 1) * 2 + 1]);
        }

        if (more) {
            *(uint4*)&As[p ^ 1][sidx]     = a0v;
            *(uint4*)&As[p ^ 1][sidx + 8] = a1v;
            *(uint4*)&Bs[p ^ 1][sidx]     = b0v;
            *(uint4*)&Bs[p ^ 1][sidx + 8] = b1v;
            __syncthreads();
        }
        p ^= 1;
    }

#pragma unroll
    for (int mt = 0; mt < 4; ++mt) {
#pragma unroll
        for (int nt = 0; nt < 4; ++nt) {
            int row = m0 + wm * 64 + mt * 16 + (lane >> 2);
            int cl  = wn * 32 + nt * 8 + (lane & 3) * 2;
            float2 v0 = { acc[mt][nt][0] + bsm[cl], acc[mt][nt][1] + bsm[cl + 1] };
            float2 v1 = { acc[mt][nt][2] + bsm[cl], acc[mt][nt][3] + bsm[cl + 1] };
            *(float2*)&g_Xproj[(size_t)row * N4H + n0 + cl]       = v0;
            *(float2*)&g_Xproj[(size_t)(row + 8) * N4H + n0 + cl] = v1;
        }
    }
}

// ---------------- kernel: persistent recurrence via mma.sync (v15) ----------------
// EXACT R11 champion structure (128 CTAs x 256 thr; kh = w>>2 K-halves; wn = w&3;
// per-domain atomic ticket barrier) with ONE change: per-pass accumulators
// (accA1/2/3, accB1/2/3) to break the HMMA RAW chain; merged after the K loop.
#define LS_W 520   // smem row stride (512 + 8 pad) in bf16
#define RED_OFF (2*64*LS_W + 2*16*LS_W)                       // bf16 units
#define LSTM_SMEM_BYTES (RED_OFF * 2 + 4*32*8*4 + 2*256*4)    // 166400+4096+2048

__global__ __launch_bounds__(256, 1) void lstm_mma() {
    extern __shared__ __nv_bfloat16 sm[];
    __nv_bfloat16* Wh = sm;                    // [64][LS_W]
    __nv_bfloat16* Wl = Wh + 64 * LS_W;
    __nv_bfloat16* Ah = Wl + 64 * LS_W;        // [16][LS_W]
    __nv_bfloat16* Al = Ah + 16 * LS_W;
    float* red = (float*)(sm + RED_OFF);       // [4*32][8]
    unsigned* htile = (unsigned*)(red + 4 * 32 * 8);   // [256]
    unsigned* ctile = htile + 256;

    const int r    = blockIdx.x;
    const int jg   = r & 31;
    const int bg   = r >> 5;
    const int t    = threadIdx.x;
    const int w    = t >> 5;
    const int lane = t & 31;
    const int kh   = w >> 2;        // K half
    const int wn   = w & 3;         // col group of 16

    // stage W^T hi/lo slices once (64 rows x 512 bf16 each)
    for (int idx = t; idx < 64 * 64; idx += 256) {
        int row = idx >> 6, ch = idx & 63;
        uint4 vh = *(const uint4*)&g_Whh[(size_t)(jg * 64 + row) * KDIM + ch * 8];
        uint4 vl = *(const uint4*)&g_Whl[(size_t)(jg * 64 + row) * KDIM + ch * 8];
        *(uint4*)&Wh[row * LS_W + ch * 8] = vh;
        *(uint4*)&Wl[row * LS_W + ch * 8] = vl;
    }
    __syncthreads();

    // ldsm element offsets (validated layout from R10/R11)
    const uint32_t Ah0 = smem_u32(Ah), Al0 = smem_u32(Al);
    const uint32_t Wh0 = smem_u32(Wh), Wl0 = smem_u32(Wl);
    const int kbase = kh * 256;
    const uint32_t aoff = (uint32_t)((((lane & 7) + ((lane >> 3) & 1) * 8) * LS_W
                                      + kbase + ((lane >> 4) & 1) * 8) * 2);
    const uint32_t boff = (uint32_t)(((wn * 16 + (lane & 7) + ((lane >> 4) & 1) * 8) * LS_W
                                      + kbase + ((lane >> 3) & 1) * 8) * 2);

    // epilogue assignment (warps 0-3): 2 outputs per lane
    const int qq    = (lane & 3) >> 1;
    const int odd   = lane & 1;
    const int b_l   = (lane >> 2) + odd * 8;
    const int hidA  = wn * 4 + qq;       // from n8#0
    const int hidB  = wn * 4 + 2 + qq;   // from n8#1
    const int b_g   = bg * 16 + b_l;

    float cstA = 0.0f, cstB = 0.0f;
    float4 xpA, xpB;
    if (w < 4) {
        xpA = __ldg((const float4*)(g_Xproj + (size_t)b_g * N4H + (jg * 16 + hidA) * 4));
        xpB = __ldg((const float4*)(g_Xproj + (size_t)b_g * N4H + (jg * 16 + hidB) * 4));
    }

    for (int step = 0; step < T_STEPS; ++step) {
        float accA[4] = {0.f, 0.f, 0.f, 0.f};
        float accB[4] = {0.f, 0.f, 0.f, 0.f};

        if (step > 0) {
            // ---- stage A (hi/lo): warp w stages batch rows w*2, w*2+1 ----
            const unsigned* src = g_hx + (size_t)(step - 1) * HB + (size_t)(bg * 16) * DIMH;
#pragma unroll
            for (int bb = 0; bb < 2; ++bb) {
                int brow = w * 2 + bb;
#pragma unroll
                for (int q = 0; q < 4; ++q) {
                    uint4 v = __ldcg((const uint4*)(src + (size_t)brow * DIMH + q * 128 + lane * 4));
                    uint2 hhv, llv;
                    hhv.x = (v.x & 0xffffu) | (v.y << 16);
                    hhv.y = (v.z & 0xffffu) | (v.w << 16);
                    llv.x = (v.x >> 16) | (v.y & 0xffff0000u);
                    llv.y = (v.z >> 16) | (v.w & 0xffff0000u);
                    *(uint2*)&Ah[brow * LS_W + q * 128 + lane * 4] = hhv;
                    *(uint2*)&Al[brow * LS_W + q * 128 + lane * 4] = llv;
                }
            }
            __syncthreads();

            // ---- 16 ksteps x (4 ldsm + 6 hmma): per-pass accumulators break
            //      the RAW chain (6 independent HMMA per kstep) ----
            float accA1[4] = {0.f, 0.f, 0.f, 0.f};
            float accA2[4] = {0.f, 0.f, 0.f, 0.f};
            float accA3[4] = {0.f, 0.f, 0.f, 0.f};
            float accB1[4] = {0.f, 0.f, 0.f, 0.f};
            float accB2[4] = {0.f, 0.f, 0.f, 0.f};
            float accB3[4] = {0.f, 0.f, 0.f, 0.f};
#pragma unroll
            for (int ks = 0; ks < 16; ++ks) {
                const uint32_t kofs = (uint32_t)(ks * 16 * 2);
                uint32_t afh[4], afl[4], bh[4], bl[4];
                ldsm_x4(afh, Ah0 + aoff + kofs);
                ldsm_x4(afl, Al0 + aoff + kofs);
                ldsm_x4(bh,  Wh0 + boff + kofs);
                ldsm_x4(bl,  Wl0 + boff + kofs);
                hmma16816(accA1, afh, bh[0], bh[1]);
                hmma16816(accB1, afh, bh[2], bh[3]);
                hmma16816(accA2, afl, bh[0], bh[1]);
                hmma16816(accB2, afl, bh[2], bh[3]);
                hmma16816(accA3, afh, bl[0], bl[1]);
                hmma16816(accB3, afh, bl[2], bl[3]);
            }
#pragma unroll
            for (int q = 0; q < 4; ++q) {
                accA[q] = accA1[q] + accA2[q] + accA3[q];
                accB[q] = accB1[q] + accB2[q] + accB3[q];
            }

            // K-half 1 warps publish partials
            if (kh == 1) {
                float* rd = red + ((size_t)wn * 32 + lane) * 8;
                *(float4*)(rd)     = *(float4*)accA;
                *(float4*)(rd + 4) = *(float4*)accB;
            }
        }
        __syncthreads();

        if (w < 4) {
            if (step > 0) {
                const float* rd = red + ((size_t)wn * 32 + lane) * 8;
                float4 pA = *(const float4*)(rd);
                float4 pB = *(const float4*)(rd + 4);
                accA[0] += pA.x; accA[1] += pA.y; accA[2] += pA.z; accA[3] += pA.w;
                accB[0] += pB.x; accB[1] += pB.y; accB[2] += pB.z; accB[3] += pB.w;
            }
            // gate combine within lane pairs (xor 1)
            float eA0 = __shfl_xor_sync(0xffffffffu, accA[0], 1);
            float eA1 = __shfl_xor_sync(0xffffffffu, accA[1], 1);
            float eA2 = __shfl_xor_sync(0xffffffffu, accA[2], 1);
            float eA3 = __shfl_xor_sync(0xffffffffu, accA[3], 1);
            float eB0 = __shfl_xor_sync(0xffffffffu, accB[0], 1);
            float eB1 = __shfl_xor_sync(0xffffffffu, accB[1], 1);
            float eB2 = __shfl_xor_sync(0xffffffffu, accB[2], 1);
            float eB3 = __shfl_xor_sync(0xffffffffu, accB[3], 1);

            float zfA = (odd ? eA2 : accA[0]) + xpA.x;
            float ziA = (odd ? eA3 : accA[1]) + xpA.y;
            float zgA = (odd ? accA[2] : eA0) + xpA.z;
            float zoA = (odd ? accA[3] : eA1) + xpA.w;
            float zfB = (odd ? eB2 : accB[0]) + xpB.x;
            float ziB = (odd ? eB3 : accB[1]) + xpB.y;
            float zgB = (odd ? accB[2] : eB0) + xpB.z;
            float zoB = (odd ? accB[3] : eB1) + xpB.w;

            cstA = sigf(zfA) * cstA + sigf(ziA) * tanh_(zgA);
            cstB = sigf(zfB) * cstB + sigf(ziB) * tanh_(zgB);
            float hA = sigf(zoA) * tanh_(cstA);
            float hB = sigf(zoB) * tanh_(cstB);

            htile[b_l * 16 + hidA] = pack_hl(hA);
            htile[b_l * 16 + hidB] = pack_hl(hB);
            if (step == T_STEPS - 1) {
                ctile[b_l * 16 + hidA] = pack_hl(cstA);
                ctile[b_l * 16 + hidB] = pack_hl(cstB);
            }
            if (step + 1 < T_STEPS) {
                xpA = __ldg((const float4*)(g_Xproj
                        + ((size_t)(step + 1) * BATCH + b_g) * N4H + (jg * 16 + hidA) * 4));
                xpB = __ldg((const float4*)(g_Xproj
                        + ((size_t)(step + 1) * BATCH + b_g) * N4H + (jg * 16 + hidB) * 4));
            }
        }

        __syncthreads();
        // coalesced h' store: thread t -> (b = t>>4, hid = t&15)
        g_hx[(size_t)step * HB + (size_t)(bg * 16 + (t >> 4)) * DIMH + jg * 16 + (t & 15)]
            = htile[t];
        if (step == T_STEPS - 1)
            g_cx[(size_t)(bg * 16 + (t >> 4)) * DIMH + jg * 16 + (t & 15)] = ctile[t];

        // ---- per-domain atomic ticket barrier (proven; 32 CTAs) ----
        __threadfence();
        __syncthreads();
        if (t == 0) {
            unsigned long long tk = atomicAdd(&g_tickd[bg * 16], 1ULL);
            unsigned long long gen = tk >> 5;
            if ((tk & 31ULL) == 31ULL) {
                __threadfence();
                g_reld[bg * 16] = gen + 1ULL;
            } else {
                while (g_reld[bg * 16] <= gen) { }
                __threadfence();
            }
        }
        __syncthreads();
    }
}

// ---------------- kernel: emit final output (unpack bf16 hi/lo -> fp32) ----------
__global__ __launch_bounds__(512) void emit_out(float* __restrict__ out, int out_size) {
    const int bx = blockIdx.x;        // 0..511: step t; 512: hx tail; 513: cx tail
    const int i4 = blockIdx.y * 512 + threadIdx.x;
    const size_t tail = (size_t)T_STEPS * HB;
    const bool write_state = (size_t)out_size >= tail + 2u * HB;

    const unsigned* src;
    float* dst;
    if (bx < T_STEPS) {
        src = g_hx + (size_t)bx * HB;
        dst = out + (size_t)bx * HB;
    } else if (bx == T_STEPS) {
        if (!write_state) return;
        src = g_hx + (size_t)(T_STEPS - 1) * HB;
        dst = out + tail;
    } else {
        if (!write_state) return;
        src = g_cx;
        dst = out + tail + HB;
    }
    uint4 v = *(const uint4*)(src + (size_t)i4 * 4);
    float4 o;
    o.x = unpack_hl(v.x);
    o.y = unpack_hl(v.y);
    o.z = unpack_hl(v.z);
    o.w = unpack_hl(v.w);
    *(float4*)(dst + (size_t)i4 * 4) = o;
}

// ---------------- launch ----------------------------------------------------------
extern "C" void kernel_launch(void* const* d_in, const int* in_sizes, int n_in,
                              void* d_out, int out_size) {
    const float* inputs = (const float*)d_in[0];
    const float* Wf = (const float*)d_in[1];
    const float* bf = (const float*)d_in[2];
    const float* Wi = (const float*)d_in[3];
    const float* bi = (const float*)d_in[4];
    const float* Wg = (const float*)d_in[5];
    const float* bg = (const float*)d_in[6];
    const float* Wo = (const float*)d_in[7];
    const float* bo = (const float*)d_in[8];

    pack_a<<<1024, 256>>>(inputs);
    pack_b<<<256, 256>>>(Wf, Wi, Wg, Wo);

    dim3 gx(N4H / XBN, MROWS / XBM);   // (16, 256)
    xproj_mma<<<gx, 256>>>(bf, bi, bg, bo);

    cudaFuncSetAttribute(lstm_mma, cudaFuncAttributeMaxDynamicSharedMemorySize, LSTM_SMEM_BYTES);
    lstm_mma<<<128, 256, LSTM_SMEM_BYTES>>>();

    emit_out<<<dim3(T_STEPS + 2, HB / 2048), 512>>>((float*)d_out, out_size);
}